// round 4
// baseline (speedup 1.0000x reference)
#include <cuda_runtime.h>
#include <math.h>

// Problem constants: B=2, S=2048, D_MODEL=1024, HEADS=16, D_K=64, D_FF=4096
// Tokens M = 4096.

#define BM 128
#define BN 128
#define BK 16

// -------- scratch (static __device__ arrays; no allocations) --------
__device__ float g_q  [4096 * 1024];
__device__ float g_k  [4096 * 1024];
__device__ float g_v  [4096 * 1024];
__device__ float g_ctx[4096 * 1024];
__device__ float g_y  [4096 * 1024];
__device__ float g_x  [4096 * 1024];
__device__ float g_ff [4096 * 4096];
__device__ float g_y2 [4096 * 1024];

// =====================================================================
// GEMM: C[M,N] = act( (A (+A2)) @ W + bias (+R) )
// Row-major A[M,K], W[K,N]. M,N,K multiples of 128/128/16 (guaranteed here).
// 256 threads, 8x8 per thread, double-buffered smem.
// =====================================================================
template <bool ADD_A2, bool RELU, bool RESID>
__global__ __launch_bounds__(256, 2)
void gemm_kernel(const float* __restrict__ A, const float* __restrict__ A2,
                 const float* __restrict__ W, const float* __restrict__ bias,
                 const float* __restrict__ R, float* __restrict__ C,
                 int M, int N, int K)
{
    __shared__ float As[2][BK][BM + 4];   // stored transposed [k][m], padded
    __shared__ float Bs[2][BK][BN];

    const int tid = threadIdx.x;
    const int tx  = tid & 15;
    const int ty  = tid >> 4;
    const int bm  = blockIdx.y * BM;
    const int bn  = blockIdx.x * BN;

    // A tile: 128x16 = 512 float4, 2 per thread
    const int ar0 = tid >> 2;             // 0..63
    const int ak0 = (tid & 3) << 2;       // 0,4,8,12
    const int ar1 = ar0 + 64;
    // B tile: 16x128 = 512 float4, 2 per thread
    const int br0 = tid >> 5;             // 0..7
    const int bc0 = (tid & 31) << 2;      // 0..124
    const int br1 = br0 + 8;

    const float* Arow0 = A + (size_t)(bm + ar0) * K;
    const float* Arow1 = A + (size_t)(bm + ar1) * K;

    float acc[8][8];
    #pragma unroll
    for (int i = 0; i < 8; i++)
        #pragma unroll
        for (int j = 0; j < 8; j++) acc[i][j] = 0.f;

    auto fetch = [&](int kt, float4& a0, float4& a1, float4& b0, float4& b1) {
        const size_t ko = (size_t)kt * BK;
        a0 = *(const float4*)(Arow0 + ko + ak0);
        a1 = *(const float4*)(Arow1 + ko + ak0);
        if constexpr (ADD_A2) {
            const float4 p0 = *(const float4*)(A2 + (size_t)(bm + ar0) * K + ko + ak0);
            const float4 p1 = *(const float4*)(A2 + (size_t)(bm + ar1) * K + ko + ak0);
            a0.x += p0.x; a0.y += p0.y; a0.z += p0.z; a0.w += p0.w;
            a1.x += p1.x; a1.y += p1.y; a1.z += p1.z; a1.w += p1.w;
        }
        b0 = *(const float4*)(W + (ko + br0) * (size_t)N + bn + bc0);
        b1 = *(const float4*)(W + (ko + br1) * (size_t)N + bn + bc0);
    };
    auto stage = [&](int buf, const float4& a0, const float4& a1,
                     const float4& b0, const float4& b1) {
        As[buf][ak0 + 0][ar0] = a0.x;  As[buf][ak0 + 1][ar0] = a0.y;
        As[buf][ak0 + 2][ar0] = a0.z;  As[buf][ak0 + 3][ar0] = a0.w;
        As[buf][ak0 + 0][ar1] = a1.x;  As[buf][ak0 + 1][ar1] = a1.y;
        As[buf][ak0 + 2][ar1] = a1.z;  As[buf][ak0 + 3][ar1] = a1.w;
        *(float4*)&Bs[buf][br0][bc0] = b0;
        *(float4*)&Bs[buf][br1][bc0] = b1;
    };

    {
        float4 a0, a1, b0, b1;
        fetch(0, a0, a1, b0, b1);
        stage(0, a0, a1, b0, b1);
    }
    __syncthreads();

    const int nt = K >> 4;
    for (int kt = 0; kt < nt; kt++) {
        const int cur = kt & 1;
        const bool pre = (kt + 1 < nt);
        float4 na0, na1, nb0, nb1;
        if (pre) fetch(kt + 1, na0, na1, nb0, nb1);

        #pragma unroll
        for (int k = 0; k < BK; k++) {
            float a[8], b[8];
            *(float4*)&a[0] = *(const float4*)&As[cur][k][ty * 4];
            *(float4*)&a[4] = *(const float4*)&As[cur][k][64 + ty * 4];
            *(float4*)&b[0] = *(const float4*)&Bs[cur][k][tx * 4];
            *(float4*)&b[4] = *(const float4*)&Bs[cur][k][64 + tx * 4];
            #pragma unroll
            for (int i = 0; i < 8; i++)
                #pragma unroll
                for (int j = 0; j < 8; j++)
                    acc[i][j] += a[i] * b[j];
        }

        if (pre) {
            stage(cur ^ 1, na0, na1, nb0, nb1);
            __syncthreads();
        }
    }

    // epilogue
    #pragma unroll
    for (int i = 0; i < 8; i++) {
        const int r = bm + ((i < 4) ? (ty * 4 + i) : (64 + ty * 4 + (i - 4)));
        #pragma unroll
        for (int jh = 0; jh < 2; jh++) {
            const int c = bn + jh * 64 + tx * 4;
            const float4 bv = *(const float4*)(bias + c);
            float4 v;
            v.x = acc[i][jh * 4 + 0] + bv.x;
            v.y = acc[i][jh * 4 + 1] + bv.y;
            v.z = acc[i][jh * 4 + 2] + bv.z;
            v.w = acc[i][jh * 4 + 3] + bv.w;
            if constexpr (RESID) {
                const float4 rv = *(const float4*)(R + (size_t)r * N + c);
                v.x += rv.x; v.y += rv.y; v.z += rv.z; v.w += rv.w;
            }
            if constexpr (RELU) {
                v.x = fmaxf(v.x, 0.f); v.y = fmaxf(v.y, 0.f);
                v.z = fmaxf(v.z, 0.f); v.w = fmaxf(v.w, 0.f);
            }
            *(float4*)(C + (size_t)r * N + c) = v;
        }
    }
}

// =====================================================================
// Flash attention with additive corr bias.
// grid = (S/128, B*H), 128 threads. One query per thread; Q and O in regs.
// scores = (Q.K)/8 + corr ; streaming online softmax.
// =====================================================================
__global__ __launch_bounds__(128, 2)
void attn_kernel(const float* __restrict__ Q, const float* __restrict__ Kp,
                 const float* __restrict__ V, const float* __restrict__ corr,
                 float* __restrict__ ctx)
{
    __shared__ float Ks[32][64];
    __shared__ float Vs[32][64];
    __shared__ float Cs[128][33];

    const int tid = threadIdx.x;
    const int q0  = blockIdx.x * 128;
    const int b   = blockIdx.y >> 4;
    const int h   = blockIdx.y & 15;

    const size_t qbase = ((size_t)(b * 2048 + q0 + tid)) * 1024 + h * 64;
    float Qr[64];
    #pragma unroll
    for (int i = 0; i < 16; i++) {
        const float4 t = *(const float4*)(Q + qbase + i * 4);
        Qr[i * 4 + 0] = t.x * 0.125f;  Qr[i * 4 + 1] = t.y * 0.125f;
        Qr[i * 4 + 2] = t.z * 0.125f;  Qr[i * 4 + 3] = t.w * 0.125f;
    }
    float Or[64];
    #pragma unroll
    for (int d = 0; d < 64; d++) Or[d] = 0.f;
    float m = -1e30f, l = 0.f;

    const size_t kvbase = (size_t)b * 2048 * 1024 + h * 64;
    const size_t cbase  = ((size_t)b * 2048 + q0) * 2048;

    for (int k0 = 0; k0 < 2048; k0 += 32) {
        // stage K, V tiles (coalesced)
        #pragma unroll
        for (int i = 0; i < 4; i++) {
            const int f = tid + i * 128;
            const int row = f >> 4;
            const int c4  = (f & 15) << 2;
            const size_t g = kvbase + (size_t)(k0 + row) * 1024 + c4;
            *(float4*)&Ks[row][c4] = *(const float4*)(Kp + g);
            *(float4*)&Vs[row][c4] = *(const float4*)(V + g);
        }
        // stage corr block [128 q][32 k] (coalesced, padded smem)
        #pragma unroll
        for (int i = 0; i < 8; i++) {
            const int f = tid + i * 128;
            const int row = f >> 3;
            const int c4  = (f & 7) << 2;
            const float4 cv = *(const float4*)(corr + cbase + (size_t)row * 2048 + k0 + c4);
            Cs[row][c4 + 0] = cv.x; Cs[row][c4 + 1] = cv.y;
            Cs[row][c4 + 2] = cv.z; Cs[row][c4 + 3] = cv.w;
        }
        __syncthreads();

        #pragma unroll 2
        for (int j = 0; j < 32; j++) {
            const float4* kr = (const float4*)Ks[j];
            float s0 = Cs[tid][j], s1 = 0.f, s2 = 0.f, s3 = 0.f;
            #pragma unroll
            for (int d4 = 0; d4 < 16; d4++) {
                const float4 kv = kr[d4];
                s0 += Qr[d4 * 4 + 0] * kv.x;
                s1 += Qr[d4 * 4 + 1] * kv.y;
                s2 += Qr[d4 * 4 + 2] * kv.z;
                s3 += Qr[d4 * 4 + 3] * kv.w;
            }
            const float s = (s0 + s1) + (s2 + s3);
            float p;
            if (s > m) {
                const float sc = __expf(m - s);   // 0 on first hit (m=-1e30)
                l *= sc;
                #pragma unroll
                for (int d = 0; d < 64; d++) Or[d] *= sc;
                m = s;
                p = 1.f;
            } else {
                p = __expf(s - m);
            }
            l += p;
            const float4* vr = (const float4*)Vs[j];
            #pragma unroll
            for (int d4 = 0; d4 < 16; d4++) {
                const float4 vv = vr[d4];
                Or[d4 * 4 + 0] += p * vv.x;
                Or[d4 * 4 + 1] += p * vv.y;
                Or[d4 * 4 + 2] += p * vv.z;
                Or[d4 * 4 + 3] += p * vv.w;
            }
        }
        __syncthreads();
    }

    const float inv = 1.f / l;
    #pragma unroll
    for (int i = 0; i < 16; i++) {
        float4 o;
        o.x = Or[i * 4 + 0] * inv;  o.y = Or[i * 4 + 1] * inv;
        o.z = Or[i * 4 + 2] * inv;  o.w = Or[i * 4 + 3] * inv;
        *(float4*)(ctx + qbase + i * 4) = o;
    }
}

// =====================================================================
// LayerNorm over last dim (1024). One CTA (256 threads) per row; exactly
// one float4 per thread.
// =====================================================================
__global__ __launch_bounds__(256)
void ln_kernel(const float* __restrict__ in, const float* __restrict__ g,
               const float* __restrict__ b, float* __restrict__ out)
{
    __shared__ float rs[8], rq[8];
    const int tid = threadIdx.x;
    const size_t base = (size_t)blockIdx.x * 1024;

    const float4 v = *(const float4*)(in + base + tid * 4);
    float s  = v.x + v.y + v.z + v.w;
    float q2 = v.x * v.x + v.y * v.y + v.z * v.z + v.w * v.w;
    #pragma unroll
    for (int o = 16; o > 0; o >>= 1) {
        s  += __shfl_xor_sync(0xffffffffu, s,  o);
        q2 += __shfl_xor_sync(0xffffffffu, q2, o);
    }
    if ((tid & 31) == 0) { rs[tid >> 5] = s; rq[tid >> 5] = q2; }
    __syncthreads();
    float ts = 0.f, tq = 0.f;
    #pragma unroll
    for (int w = 0; w < 8; w++) { ts += rs[w]; tq += rq[w]; }

    const float mu  = ts * (1.f / 1024.f);
    const float var = tq * (1.f / 1024.f) - mu * mu;
    const float invs = rsqrtf(var + 1e-5f);

    const float4 gg = *(const float4*)(g + tid * 4);
    const float4 bb = *(const float4*)(b + tid * 4);
    float4 o;
    o.x = (v.x - mu) * invs * gg.x + bb.x;
    o.y = (v.y - mu) * invs * gg.y + bb.y;
    o.z = (v.z - mu) * invs * gg.z + bb.z;
    o.w = (v.w - mu) * invs * gg.w + bb.w;
    *(float4*)(out + base + tid * 4) = o;
}

// =====================================================================
extern "C" void kernel_launch(void* const* d_in, const int* in_sizes, int n_in,
                              void* d_out, int out_size)
{
    (void)in_sizes; (void)n_in; (void)out_size;
    const float* src  = (const float*)d_in[0];
    const float* corr = (const float*)d_in[1];
    const float* pos  = (const float*)d_in[2];
    const float* Wq   = (const float*)d_in[3];
    const float* bq   = (const float*)d_in[4];
    const float* Wk   = (const float*)d_in[5];
    const float* bk   = (const float*)d_in[6];
    const float* Wv   = (const float*)d_in[7];
    const float* bv   = (const float*)d_in[8];
    const float* Wo   = (const float*)d_in[9];
    const float* bo   = (const float*)d_in[10];
    const float* W1   = (const float*)d_in[11];
    const float* b1   = (const float*)d_in[12];
    const float* W2   = (const float*)d_in[13];
    const float* b2   = (const float*)d_in[14];
    const float* g1   = (const float*)d_in[15];
    const float* be1  = (const float*)d_in[16];
    const float* g2   = (const float*)d_in[17];
    const float* be2  = (const float*)d_in[18];
    float* out = (float*)d_out;

    float *q, *k, *v, *ctx, *y, *x, *ff, *y2;
    cudaGetSymbolAddress((void**)&q,   g_q);
    cudaGetSymbolAddress((void**)&k,   g_k);
    cudaGetSymbolAddress((void**)&v,   g_v);
    cudaGetSymbolAddress((void**)&ctx, g_ctx);
    cudaGetSymbolAddress((void**)&y,   g_y);
    cudaGetSymbolAddress((void**)&x,   g_x);
    cudaGetSymbolAddress((void**)&ff,  g_ff);
    cudaGetSymbolAddress((void**)&y2,  g_y2);

    const dim3 gProj(1024 / BN, 4096 / BM);   // (8, 32)
    const dim3 gFF1 (4096 / BN, 4096 / BM);   // (32, 32)

    // Q/K projections use (src + pos), V uses raw src
    gemm_kernel<true,  false, false><<<gProj, 256>>>(src, pos,     Wq, bq, nullptr, q,  4096, 1024, 1024);
    gemm_kernel<true,  false, false><<<gProj, 256>>>(src, pos,     Wk, bk, nullptr, k,  4096, 1024, 1024);
    gemm_kernel<false, false, false><<<gProj, 256>>>(src, nullptr, Wv, bv, nullptr, v,  4096, 1024, 1024);

    attn_kernel<<<dim3(2048 / 128, 32), 128>>>(q, k, v, corr, ctx);

    // output projection + residual (src)
    gemm_kernel<false, false, true ><<<gProj, 256>>>(ctx, nullptr, Wo, bo, src, y, 4096, 1024, 1024);
    ln_kernel<<<4096, 256>>>(y, g1, be1, x);

    // FFN: relu(x@W1+b1) @ W2 + b2 + x, then LN -> out
    gemm_kernel<false, true,  false><<<gFF1,  256>>>(x,  nullptr, W1, b1, nullptr, ff, 4096, 4096, 1024);
    gemm_kernel<false, false, true ><<<gProj, 256>>>(ff, nullptr, W2, b2, x,       y2, 4096, 1024, 4096);
    ln_kernel<<<4096, 256>>>(y2, g2, be2, out);
}

// round 6
// speedup vs baseline: 1.5084x; 1.5084x over previous
#include <cuda_runtime.h>
#include <cuda_bf16.h>
#include <math.h>
#include <stdint.h>

// B=2, S=2048, D_MODEL=1024, HEADS=16, D_K=64, D_FF=4096, tokens M=4096

// ---------------------------------------------------------------- scratch
__device__ __align__(128) float g_q [1u<<22];
__device__ __align__(128) float g_k [1u<<22];
__device__ __align__(128) float g_v [1u<<22];
__device__ __align__(128) float g_y [1u<<22];
__device__ __align__(128) float g_x [1u<<22];
__device__ __align__(128) float g_y2[1u<<22];
__device__ __align__(128) __nv_bfloat16 g_qkin_h[1u<<22], g_qkin_l[1u<<22];
__device__ __align__(128) __nv_bfloat16 g_src_h [1u<<22], g_src_l [1u<<22];
__device__ __align__(128) __nv_bfloat16 g_ctx_h [1u<<22], g_ctx_l [1u<<22];
__device__ __align__(128) __nv_bfloat16 g_x_h   [1u<<22], g_x_l   [1u<<22];
__device__ __align__(128) __nv_bfloat16 g_ff_h  [1u<<24], g_ff_l  [1u<<24];
__device__ __align__(128) __nv_bfloat16 g_wt_h  [12u<<20], g_wt_l [12u<<20];

// ---------------------------------------------------------------- helpers
__device__ __forceinline__ uint32_t smem_u32(const void* p) {
    uint32_t a;
    asm("{ .reg .u64 t; cvta.to.shared.u64 t, %1; cvt.u32.u64 %0, t; }" : "=r"(a) : "l"(p));
    return a;
}
__device__ __forceinline__ void cp16(uint32_t dst, const void* src) {
    asm volatile("cp.async.cg.shared.global [%0], [%1], 16;"
                 :: "r"(dst), "l"(__cvta_generic_to_global(src)) : "memory");
}
#define CP_COMMIT() asm volatile("cp.async.commit_group;" ::: "memory")
#define CP_WAIT1()  asm volatile("cp.async.wait_group 1;"  ::: "memory")

#define LDSM4(r, addr) \
    asm volatile("ldmatrix.sync.aligned.m8n8.x4.shared.b16 {%0,%1,%2,%3}, [%4];" \
                 : "=r"((r)[0]), "=r"((r)[1]), "=r"((r)[2]), "=r"((r)[3]) : "r"(addr))

#define MMA16816(d, a, b) \
    asm volatile("mma.sync.aligned.m16n8k16.row.col.f32.bf16.bf16.f32 " \
                 "{%0,%1,%2,%3}, {%4,%5,%6,%7}, {%8,%9}, {%0,%1,%2,%3};" \
                 : "+f"((d)[0]), "+f"((d)[1]), "+f"((d)[2]), "+f"((d)[3]) \
                 : "r"((a)[0]), "r"((a)[1]), "r"((a)[2]), "r"((a)[3]), \
                   "r"((b)[0]), "r"((b)[1]))

__device__ __forceinline__ void split_store4(__nv_bfloat16* __restrict__ H,
                                             __nv_bfloat16* __restrict__ L, float4 v) {
    union { __nv_bfloat16 b[4]; uint2 u; } hv, lv;
    hv.b[0] = __float2bfloat16(v.x); lv.b[0] = __float2bfloat16(v.x - __bfloat162float(hv.b[0]));
    hv.b[1] = __float2bfloat16(v.y); lv.b[1] = __float2bfloat16(v.y - __bfloat162float(hv.b[1]));
    hv.b[2] = __float2bfloat16(v.z); lv.b[2] = __float2bfloat16(v.z - __bfloat162float(hv.b[2]));
    hv.b[3] = __float2bfloat16(v.w); lv.b[3] = __float2bfloat16(v.w - __bfloat162float(hv.b[3]));
    *(uint2*)H = hv.u;
    *(uint2*)L = lv.u;
}
__device__ __forceinline__ void split_store2(__nv_bfloat16* __restrict__ H,
                                             __nv_bfloat16* __restrict__ L,
                                             float x, float y) {
    union { __nv_bfloat16 b[2]; uint32_t u; } hv, lv;
    hv.b[0] = __float2bfloat16(x); lv.b[0] = __float2bfloat16(x - __bfloat162float(hv.b[0]));
    hv.b[1] = __float2bfloat16(y); lv.b[1] = __float2bfloat16(y - __bfloat162float(hv.b[1]));
    *(uint32_t*)H = hv.u;
    *(uint32_t*)L = lv.u;
}

// ================================================================ HMMA GEMM
// C[M,N] = act( A @ B^T + bias (+R) )
// A = Ah+Al [M,K] bf16 K-major; B = Bh+Bl [N,K] bf16 K-major.
// CTA 128x128, 256 threads (8 warps = 4m x 2n, warp tile 32x64),
// K chunks of 32, 3-stage cp.async pipeline, padded smem (80B rows).
#define ST      3
#define CHUNK   32
#define ROWB    80                 // bytes per smem row (40 bf16)
#define MATB    (128 * ROWB)       // 10240
#define STAGEB  (4 * MATB)         // 40960
#define GEMM_SMEM (ST * STAGEB)    // 122880

template<bool RELU, bool RESID, bool SPLIT>
__global__ __launch_bounds__(256, 1)
void gemm_tc(const __nv_bfloat16* __restrict__ Ah, const __nv_bfloat16* __restrict__ Al,
             const __nv_bfloat16* __restrict__ Bh, const __nv_bfloat16* __restrict__ Bl,
             const float* __restrict__ bias, const float* __restrict__ Rsd,
             float* __restrict__ Cf, __nv_bfloat16* __restrict__ Ch, __nv_bfloat16* __restrict__ Cl,
             int M, int N, int K)
{
    extern __shared__ __align__(128) char smem[];
    const uint32_t sb = smem_u32(smem);
    const int tid  = threadIdx.x;
    const int wid  = tid >> 5, lane = tid & 31;
    const int bm   = blockIdx.y * 128, bn = blockIdx.x * 128;
    const int m0   = (wid & 3) * 32;         // warp row offset in tile
    const int n0   = (wid >> 2) * 64;        // warp col offset in tile
    const int nt   = K / CHUNK;

    float acc[2][8][4];
    #pragma unroll
    for (int i = 0; i < 2; i++)
        #pragma unroll
        for (int j = 0; j < 8; j++)
            #pragma unroll
            for (int q = 0; q < 4; q++) acc[i][j][q] = 0.f;

    auto stage = [&](int c) {
        const uint32_t base = sb + (uint32_t)(c % ST) * STAGEB;
        const size_t kof = (size_t)c * CHUNK;
        #pragma unroll
        for (int i = 0; i < 2; i++) {
            const int f   = tid + i * 256;      // 0..511
            const int row = f >> 2, ch = f & 3;
            const uint32_t so = row * ROWB + ch * 16;
            const size_t ga = (size_t)(bm + row) * K + kof + ch * 8;
            const size_t gb = (size_t)(bn + row) * K + kof + ch * 8;
            cp16(base +            so, Ah + ga);
            cp16(base +     MATB + so, Al + ga);
            cp16(base + 2 * MATB + so, Bh + gb);
            cp16(base + 3 * MATB + so, Bl + gb);
        }
        CP_COMMIT();
    };

    stage(0);
    stage(1);

    // per-lane ldmatrix address components
    const uint32_t a_row  = m0 + (lane & 15);
    const uint32_t a_coff = (uint32_t)((lane >> 4) << 4);              // bytes
    const uint32_t b_row  = n0 + ((lane >> 4) << 3) + (lane & 7);
    const uint32_t b_coff = (uint32_t)(((lane >> 3) & 1) << 4);        // bytes

    for (int c = 0; c < nt; c++) {
        if (c + ST - 1 < nt) stage(c + ST - 1);
        else                 CP_COMMIT();
        CP_WAIT1();
        __syncthreads();

        const uint32_t base = sb + (uint32_t)(c % ST) * STAGEB;
        #pragma unroll
        for (int ks = 0; ks < 2; ks++) {
            uint32_t aH[2][4], aL[2][4], bH[8][2], bL[8][2];
            #pragma unroll
            for (int mi = 0; mi < 2; mi++) {
                const uint32_t ra = base + (a_row + mi * 16) * ROWB + ks * 32 + a_coff;
                LDSM4(aH[mi], ra);
                LDSM4(aL[mi], ra + MATB);
            }
            #pragma unroll
            for (int t = 0; t < 4; t++) {
                const uint32_t rb = base + 2 * MATB + (b_row + t * 16) * ROWB + ks * 32 + b_coff;
                uint32_t r[4];
                LDSM4(r, rb);
                bH[2*t][0] = r[0]; bH[2*t][1] = r[1];
                bH[2*t+1][0] = r[2]; bH[2*t+1][1] = r[3];
                LDSM4(r, rb + MATB);
                bL[2*t][0] = r[0]; bL[2*t][1] = r[1];
                bL[2*t+1][0] = r[2]; bL[2*t+1][1] = r[3];
            }
            #pragma unroll
            for (int mi = 0; mi < 2; mi++)
                #pragma unroll
                for (int ni = 0; ni < 8; ni++) {
                    MMA16816(acc[mi][ni], aH[mi], bH[ni]);
                    MMA16816(acc[mi][ni], aL[mi], bH[ni]);
                    MMA16816(acc[mi][ni], aH[mi], bL[ni]);
                }
        }
        __syncthreads();
    }

    // epilogue: fragment -> global
    #pragma unroll
    for (int mi = 0; mi < 2; mi++) {
        #pragma unroll
        for (int half = 0; half < 2; half++) {
            const int r = bm + m0 + mi * 16 + half * 8 + (lane >> 2);
            const size_t orow = (size_t)r * N;
            #pragma unroll
            for (int ni = 0; ni < 8; ni++) {
                const int cc = bn + n0 + ni * 8 + (lane & 3) * 2;
                float vx = acc[mi][ni][half * 2 + 0];
                float vy = acc[mi][ni][half * 2 + 1];
                const float2 b2 = *(const float2*)(bias + cc);
                vx += b2.x; vy += b2.y;
                if constexpr (RESID) {
                    const float2 rr = *(const float2*)(Rsd + orow + cc);
                    vx += rr.x; vy += rr.y;
                }
                if constexpr (RELU) { vx = fmaxf(vx, 0.f); vy = fmaxf(vy, 0.f); }
                if constexpr (SPLIT) split_store2(Ch + orow + cc, Cl + orow + cc, vx, vy);
                else { float2 o; o.x = vx; o.y = vy; *(float2*)(Cf + orow + cc) = o; }
            }
        }
    }
}

// ================================================================ weight transpose+split
// W[K,N] fp32 -> Th,Tl[N,K] bf16
__global__ __launch_bounds__(256)
void tsplit_kernel(const float* __restrict__ W, __nv_bfloat16* __restrict__ Th,
                   __nv_bfloat16* __restrict__ Tl, int K, int N)
{
    __shared__ float t[32][33];
    const int n0 = blockIdx.x * 32, k0 = blockIdx.y * 32;
    const int tx = threadIdx.x, ty = threadIdx.y;
    #pragma unroll
    for (int i = 0; i < 32; i += 8)
        t[ty + i][tx] = W[(size_t)(k0 + ty + i) * N + n0 + tx];
    __syncthreads();
    #pragma unroll
    for (int i = 0; i < 32; i += 8) {
        const float v = t[tx][ty + i];
        const __nv_bfloat16 h = __float2bfloat16(v);
        const __nv_bfloat16 l = __float2bfloat16(v - __bfloat162float(h));
        const size_t o = (size_t)(n0 + ty + i) * K + k0 + tx;
        Th[o] = h; Tl[o] = l;
    }
}

// activation split (optionally a+b first)
template<bool ADD>
__global__ __launch_bounds__(256)
void split_kernel(const float* __restrict__ a, const float* __restrict__ b,
                  __nv_bfloat16* __restrict__ H, __nv_bfloat16* __restrict__ L)
{
    const size_t i = ((size_t)blockIdx.x * 256 + threadIdx.x) * 4;
    float4 v = *(const float4*)(a + i);
    if constexpr (ADD) {
        const float4 w = *(const float4*)(b + i);
        v.x += w.x; v.y += w.y; v.z += w.z; v.w += w.w;
    }
    split_store4(H + i, L + i, v);
}

// ================================================================ flash attention (fp32 SIMT)
__global__ __launch_bounds__(128, 2)
void attn_kernel(const float* __restrict__ Q, const float* __restrict__ Kp,
                 const float* __restrict__ V, const float* __restrict__ corr,
                 __nv_bfloat16* __restrict__ ctx_h, __nv_bfloat16* __restrict__ ctx_l)
{
    __shared__ float Ks[32][64];
    __shared__ float Vs[32][64];
    __shared__ float Cs[128][33];

    const int tid = threadIdx.x;
    const int q0  = blockIdx.x * 128;
    const int b   = blockIdx.y >> 4;
    const int h   = blockIdx.y & 15;

    const size_t qbase = ((size_t)(b * 2048 + q0 + tid)) * 1024 + h * 64;
    float Qr[64];
    #pragma unroll
    for (int i = 0; i < 16; i++) {
        const float4 t = *(const float4*)(Q + qbase + i * 4);
        Qr[i*4+0] = t.x * 0.125f;  Qr[i*4+1] = t.y * 0.125f;
        Qr[i*4+2] = t.z * 0.125f;  Qr[i*4+3] = t.w * 0.125f;
    }
    float Or[64];
    #pragma unroll
    for (int d = 0; d < 64; d++) Or[d] = 0.f;
    float m = -1e30f, l = 0.f;

    const size_t kvbase = (size_t)b * 2048 * 1024 + h * 64;
    const size_t cbase  = ((size_t)b * 2048 + q0) * 2048;

    for (int k0 = 0; k0 < 2048; k0 += 32) {
        #pragma unroll
        for (int i = 0; i < 4; i++) {
            const int f = tid + i * 128;
            const int row = f >> 4;
            const int c4  = (f & 15) << 2;
            const size_t g = kvbase + (size_t)(k0 + row) * 1024 + c4;
            *(float4*)&Ks[row][c4] = *(const float4*)(Kp + g);
            *(float4*)&Vs[row][c4] = *(const float4*)(V + g);
        }
        #pragma unroll
        for (int i = 0; i < 8; i++) {
            const int f = tid + i * 128;
            const int row = f >> 3;
            const int c4  = (f & 7) << 2;
            const float4 cv = *(const float4*)(corr + cbase + (size_t)row * 2048 + k0 + c4);
            Cs[row][c4+0] = cv.x; Cs[row][c4+1] = cv.y;
            Cs[row][c4+2] = cv.z; Cs[row][c4+3] = cv.w;
        }
        __syncthreads();

        #pragma unroll 2
        for (int j = 0; j < 32; j++) {
            const float4* kr = (const float4*)Ks[j];
            float s0 = Cs[tid][j], s1 = 0.f, s2 = 0.f, s3 = 0.f;
            #pragma unroll
            for (int d4 = 0; d4 < 16; d4++) {
                const float4 kv = kr[d4];
                s0 += Qr[d4*4+0] * kv.x;
                s1 += Qr[d4*4+1] * kv.y;
                s2 += Qr[d4*4+2] * kv.z;
                s3 += Qr[d4*4+3] * kv.w;
            }
            const float s = (s0 + s1) + (s2 + s3);
            float p;
            if (s > m) {
                const float sc = __expf(m - s);
                l *= sc;
                #pragma unroll
                for (int d = 0; d < 64; d++) Or[d] *= sc;
                m = s;
                p = 1.f;
            } else {
                p = __expf(s - m);
            }
            l += p;
            const float4* vr = (const float4*)Vs[j];
            #pragma unroll
            for (int d4 = 0; d4 < 16; d4++) {
                const float4 vv = vr[d4];
                Or[d4*4+0] += p * vv.x;
                Or[d4*4+1] += p * vv.y;
                Or[d4*4+2] += p * vv.z;
                Or[d4*4+3] += p * vv.w;
            }
        }
        __syncthreads();
    }

    const float inv = 1.f / l;
    #pragma unroll
    for (int i = 0; i < 16; i++) {
        float4 o;
        o.x = Or[i*4+0] * inv;  o.y = Or[i*4+1] * inv;
        o.z = Or[i*4+2] * inv;  o.w = Or[i*4+3] * inv;
        split_store4(ctx_h + qbase + i * 4, ctx_l + qbase + i * 4, o);
    }
}

// ================================================================ LayerNorm (optional bf16 split out)
template<bool SPLIT>
__global__ __launch_bounds__(256)
void ln_kernel(const float* __restrict__ in, const float* __restrict__ g,
               const float* __restrict__ b, float* __restrict__ out,
               __nv_bfloat16* __restrict__ H, __nv_bfloat16* __restrict__ L)
{
    __shared__ float rs[8], rq[8];
    const int tid = threadIdx.x;
    const size_t base = (size_t)blockIdx.x * 1024;

    const float4 v = *(const float4*)(in + base + tid * 4);
    float s  = v.x + v.y + v.z + v.w;
    float q2 = v.x*v.x + v.y*v.y + v.z*v.z + v.w*v.w;
    #pragma unroll
    for (int o = 16; o > 0; o >>= 1) {
        s  += __shfl_xor_sync(0xffffffffu, s,  o);
        q2 += __shfl_xor_sync(0xffffffffu, q2, o);
    }
    if ((tid & 31) == 0) { rs[tid >> 5] = s; rq[tid >> 5] = q2; }
    __syncthreads();
    float ts = 0.f, tq = 0.f;
    #pragma unroll
    for (int w = 0; w < 8; w++) { ts += rs[w]; tq += rq[w]; }

    const float mu   = ts * (1.f / 1024.f);
    const float var  = tq * (1.f / 1024.f) - mu * mu;
    const float invs = rsqrtf(var + 1e-5f);

    const float4 gg = *(const float4*)(g + tid * 4);
    const float4 bb = *(const float4*)(b + tid * 4);
    float4 o;
    o.x = (v.x - mu) * invs * gg.x + bb.x;
    o.y = (v.y - mu) * invs * gg.y + bb.y;
    o.z = (v.z - mu) * invs * gg.z + bb.z;
    o.w = (v.w - mu) * invs * gg.w + bb.w;
    *(float4*)(out + base + tid * 4) = o;
    if constexpr (SPLIT) split_store4(H + base + tid * 4, L + base + tid * 4, o);
}

// ================================================================ launch
extern "C" void kernel_launch(void* const* d_in, const int* in_sizes, int n_in,
                              void* d_out, int out_size)
{
    (void)in_sizes; (void)n_in; (void)out_size;
    const float* src  = (const float*)d_in[0];
    const float* corr = (const float*)d_in[1];
    const float* pos  = (const float*)d_in[2];
    const float* Wq   = (const float*)d_in[3];
    const float* bq   = (const float*)d_in[4];
    const float* Wk   = (const float*)d_in[5];
    const float* bk   = (const float*)d_in[6];
    const float* Wv   = (const float*)d_in[7];
    const float* bv   = (const float*)d_in[8];
    const float* Wo   = (const float*)d_in[9];
    const float* bo   = (const float*)d_in[10];
    const float* W1   = (const float*)d_in[11];
    const float* b1   = (const float*)d_in[12];
    const float* W2   = (const float*)d_in[13];
    const float* b2   = (const float*)d_in[14];
    const float* g1   = (const float*)d_in[15];
    const float* be1  = (const float*)d_in[16];
    const float* g2   = (const float*)d_in[17];
    const float* be2  = (const float*)d_in[18];
    float* out = (float*)d_out;

    float *q, *k, *v, *y, *x, *y2;
    __nv_bfloat16 *qkh, *qkl, *sh, *sl, *cth, *ctl, *xh, *xl, *ffh, *ffl, *wth, *wtl;
    cudaGetSymbolAddress((void**)&q,   g_q);    cudaGetSymbolAddress((void**)&k,   g_k);
    cudaGetSymbolAddress((void**)&v,   g_v);    cudaGetSymbolAddress((void**)&y,   g_y);
    cudaGetSymbolAddress((void**)&x,   g_x);    cudaGetSymbolAddress((void**)&y2,  g_y2);
    cudaGetSymbolAddress((void**)&qkh, g_qkin_h); cudaGetSymbolAddress((void**)&qkl, g_qkin_l);
    cudaGetSymbolAddress((void**)&sh,  g_src_h);  cudaGetSymbolAddress((void**)&sl,  g_src_l);
    cudaGetSymbolAddress((void**)&cth, g_ctx_h);  cudaGetSymbolAddress((void**)&ctl, g_ctx_l);
    cudaGetSymbolAddress((void**)&xh,  g_x_h);    cudaGetSymbolAddress((void**)&xl,  g_x_l);
    cudaGetSymbolAddress((void**)&ffh, g_ff_h);   cudaGetSymbolAddress((void**)&ffl, g_ff_l);
    cudaGetSymbolAddress((void**)&wth, g_wt_h);   cudaGetSymbolAddress((void**)&wtl, g_wt_l);

    // packed transposed-weight offsets (elements)
    const size_t OQ = 0, OK_ = 1u<<20, OV = 2u<<20, OO = 3u<<20, O1 = 4u<<20, O2 = 8u<<20;

    cudaFuncSetAttribute(gemm_tc<false,false,false>, cudaFuncAttributeMaxDynamicSharedMemorySize, GEMM_SMEM);
    cudaFuncSetAttribute(gemm_tc<false,true ,false>, cudaFuncAttributeMaxDynamicSharedMemorySize, GEMM_SMEM);
    cudaFuncSetAttribute(gemm_tc<true ,false,true >, cudaFuncAttributeMaxDynamicSharedMemorySize, GEMM_SMEM);

    const dim3 tb(32, 8);
    // weight transpose+split
    tsplit_kernel<<<dim3(1024/32, 1024/32), tb>>>(Wq, wth + OQ,  wtl + OQ,  1024, 1024);
    tsplit_kernel<<<dim3(1024/32, 1024/32), tb>>>(Wk, wth + OK_, wtl + OK_, 1024, 1024);
    tsplit_kernel<<<dim3(1024/32, 1024/32), tb>>>(Wv, wth + OV,  wtl + OV,  1024, 1024);
    tsplit_kernel<<<dim3(1024/32, 1024/32), tb>>>(Wo, wth + OO,  wtl + OO,  1024, 1024);
    tsplit_kernel<<<dim3(4096/32, 1024/32), tb>>>(W1, wth + O1,  wtl + O1,  1024, 4096);
    tsplit_kernel<<<dim3(1024/32, 4096/32), tb>>>(W2, wth + O2,  wtl + O2,  4096, 1024);

    // activation splits
    split_kernel<true ><<<4096, 256>>>(src, pos,     qkh, qkl);   // q/k input = src + pos
    split_kernel<false><<<4096, 256>>>(src, nullptr, sh,  sl);    // v input = src

    const dim3 gP(8, 32), gF1(32, 32);
    // projections
    gemm_tc<false,false,false><<<gP, 256, GEMM_SMEM>>>(qkh, qkl, wth + OQ,  wtl + OQ,  bq, nullptr, q,  nullptr, nullptr, 4096, 1024, 1024);
    gemm_tc<false,false,false><<<gP, 256, GEMM_SMEM>>>(qkh, qkl, wth + OK_, wtl + OK_, bk, nullptr, k,  nullptr, nullptr, 4096, 1024, 1024);
    gemm_tc<false,false,false><<<gP, 256, GEMM_SMEM>>>(sh,  sl,  wth + OV,  wtl + OV,  bv, nullptr, v,  nullptr, nullptr, 4096, 1024, 1024);

    attn_kernel<<<dim3(2048/128, 32), 128>>>(q, k, v, corr, cth, ctl);

    // output projection + residual(src) -> y ; LN1 -> x (+ bf16 split)
    gemm_tc<false,true ,false><<<gP, 256, GEMM_SMEM>>>(cth, ctl, wth + OO, wtl + OO, bo, src, y, nullptr, nullptr, 4096, 1024, 1024);
    ln_kernel<true ><<<4096, 256>>>(y, g1, be1, x, xh, xl);

    // FFN1: relu -> bf16 split directly ; FFN2 + residual(x) -> y2 ; LN2 -> out
    gemm_tc<true ,false,true ><<<gF1, 256, GEMM_SMEM>>>(xh,  xl,  wth + O1, wtl + O1, b1, nullptr, nullptr, ffh, ffl, 4096, 4096, 1024);
    gemm_tc<false,true ,false><<<gP,  256, GEMM_SMEM>>>(ffh, ffl, wth + O2, wtl + O2, b2, x,       y2, nullptr, nullptr, 4096, 1024, 4096);
    ln_kernel<false><<<4096, 256>>>(y2, g2, be2, out, nullptr, nullptr);
}